// round 12
// baseline (speedup 1.0000x reference)
#include <cuda_runtime.h>
#include <cuda_fp16.h>
#include <cstdint>

#define S_DIM 4096
#define H_DIM 1024
#define B_DIM 4

// ---------------- scratch (__device__ globals; no allocs allowed) -----------
__device__ __half g_xhi [B_DIM * S_DIM * H_DIM];
__device__ __half g_xThi[B_DIM * H_DIM * S_DIM];
__device__ __half g_xTlo[B_DIM * H_DIM * S_DIM];
__device__ __half g_WThi[H_DIM * H_DIM];
__device__ __half g_Ghi [B_DIM * H_DIM * H_DIM];
__device__ __half g_MThi[B_DIM * H_DIM * H_DIM];

// ---------------- helpers ----------------------------------------------------
__device__ __forceinline__ uint32_t smem_u32(const void* p) {
    uint32_t a;
    asm("{ .reg .u64 t; cvta.to.shared.u64 t, %1; cvt.u32.u64 %0, t; }"
        : "=r"(a) : "l"(p));
    return a;
}

#define SWZ128(off) ((off) ^ (((off) >> 3) & 0x70))

__device__ __forceinline__ void cp_async16(uint32_t dst, const void* src) {
    asm volatile("cp.async.cg.shared.global [%0], [%1], 16;" :: "r"(dst), "l"(src));
}

__device__ __forceinline__ void ldsm4(uint32_t* r, uint32_t addr) {
    asm volatile("ldmatrix.sync.aligned.m8n8.x4.shared.b16 {%0,%1,%2,%3}, [%4];"
                 : "=r"(r[0]), "=r"(r[1]), "=r"(r[2]), "=r"(r[3]) : "r"(addr));
}

__device__ __forceinline__ void mma_f16(float* d, const uint32_t* a,
                                        uint32_t b0, uint32_t b1) {
    asm volatile(
        "mma.sync.aligned.m16n8k16.row.col.f32.f16.f16.f32 "
        "{%0,%1,%2,%3}, {%4,%5,%6,%7}, {%8,%9}, {%0,%1,%2,%3};"
        : "+f"(d[0]), "+f"(d[1]), "+f"(d[2]), "+f"(d[3])
        : "r"(a[0]), "r"(a[1]), "r"(a[2]), "r"(a[3]), "r"(b0), "r"(b1));
}

// ---------------- conversion kernels ----------------------------------------
__global__ void x_conv_kernel(const float* __restrict__ in,
                              __half* __restrict__ hiN,
                              __half* __restrict__ hiT,
                              __half* __restrict__ loT,
                              int R, int C) {
    __shared__ float tile[32][33];
    long boff = (long)blockIdx.z * R * C;
    const float* src = in + boff;
    int bx = blockIdx.x * 32;
    int by = blockIdx.y * 32;
    int tx = threadIdx.x, ty = threadIdx.y;
#pragma unroll
    for (int j = 0; j < 4; ++j) {
        int row = by + ty + j * 8;
        float v = src[(long)row * C + bx + tx];
        tile[ty + j * 8][tx] = v;
        hiN[boff + (long)row * C + bx + tx] = __float2half_rn(v);
    }
    __syncthreads();
#pragma unroll
    for (int j = 0; j < 4; ++j) {
        int oc = bx + ty + j * 8;
        int orow = by + tx;
        float v = tile[tx][ty + j * 8];
        __half h = __float2half_rn(v);
        __half l = __float2half_rn(v - __half2float(h));
        hiT[boff + (long)oc * R + orow] = h;
        loT[boff + (long)oc * R + orow] = l;
    }
}

__global__ void w_conv_kernel(const float* __restrict__ in,
                              __half* __restrict__ hiT, int R, int C, float sc) {
    __shared__ float tile[32][33];
    int bx = blockIdx.x * 32;
    int by = blockIdx.y * 32;
    int tx = threadIdx.x, ty = threadIdx.y;
#pragma unroll
    for (int j = 0; j < 4; ++j)
        tile[ty + j * 8][tx] = in[(long)(by + ty + j * 8) * C + bx + tx];
    __syncthreads();
#pragma unroll
    for (int j = 0; j < 4; ++j) {
        int oc = bx + ty + j * 8;
        int orow = by + tx;
        hiT[(long)oc * R + orow] = __float2half_rn(tile[tx][ty + j * 8] * sc);
    }
}

// ---------------- GEMM1 kernel: symmetric, A split --------------------------
// G = (Ahi + Alo) . Ahi^T, upper-tri blocks, mirror via smem. fp16 out.
// CTA 128x128, KTILE=64 (128B rows), 3-stage, occ 1 (no reg cap, grid < #SM).

#define KTILE1 64
#define TILE1_B 16384                   // 128 rows * 128 B
#define STAGE1_B (3 * TILE1_B)          // Ahi, Alo, B
#define SMEM1_TOT (3 * STAGE1_B)        // 144 KB

__global__ __launch_bounds__(256, 1) void gemm_sym(
    const __half* __restrict__ P0, const __half* __restrict__ P1,
    const __half* __restrict__ PB, __half* __restrict__ Ch,
    int K, int lda, int ldc, long sA, long sC)
{
    extern __shared__ __align__(1024) unsigned char smem[];
    const uint32_t sbase = smem_u32(smem);
    const int tid = threadIdx.x;
    const int wid = tid >> 5;
    const int lane = tid & 31;
    const int warp_m = wid >> 2;
    const int warp_n = wid & 3;
    const int bz = blockIdx.z;

    int bi = 0, bj = 0;
    {
        int r = blockIdx.x;
        while (r >= 8 - bi) { r -= 8 - bi; ++bi; }
        bj = bi + r;
    }
    const int m0 = bi * 128, n0 = bj * 128;

    const __half* srcs[3];
    srcs[0] = P0 + bz * sA + (long)m0 * lda;
    srcs[1] = P1 + bz * sA + (long)m0 * lda;
    srcs[2] = PB + bz * sA + (long)n0 * lda;

    const int lr = lane & 7;
    const int lg = (lane >> 3) & 1;
    const int lk = (lane >> 4) & 1;
    const int arow = warp_m * 64 + lr + lg * 8;
    const int brow = warp_n * 32 + lr + lg * 8;
    const int colb0 = lk * 16;

    float acc[4][4][4];
#pragma unroll
    for (int i = 0; i < 4; ++i)
#pragma unroll
        for (int j = 0; j < 4; ++j)
#pragma unroll
            for (int c = 0; c < 4; ++c) acc[i][j][c] = 0.0f;

    const int T = K / KTILE1;

    auto load_tile = [&](int p, int k0) {
        uint32_t dst0 = sbase + (uint32_t)p * STAGE1_B;
#pragma unroll
        for (int i = 0; i < 12; ++i) {
            int cid = tid + i * 256;
            int sub = cid >> 10;
            int idx = cid & 1023;
            int row = idx >> 3;
            int ck = idx & 7;
            const __half* src = srcs[sub] + (long)row * lda + k0 + ck * 8;
            uint32_t off = (uint32_t)(row * 128 + ck * 16);
            cp_async16(dst0 + (uint32_t)sub * TILE1_B + SWZ128(off), src);
        }
        asm volatile("cp.async.commit_group;");
    };

    load_tile(0, 0);
    load_tile(1, KTILE1);

    for (int t = 0; t < T; ++t) {
        if (t + 1 < T) asm volatile("cp.async.wait_group 1;");
        else           asm volatile("cp.async.wait_group 0;");
        __syncthreads();
        if (t + 2 < T) load_tile((t + 2) % 3, (t + 2) * KTILE1);

        const uint32_t st = sbase + (uint32_t)(t % 3) * STAGE1_B;
        const uint32_t ta_hi = st;
        const uint32_t ta_lo = st + TILE1_B;
        const uint32_t tb_   = st + 2 * TILE1_B;

#pragma unroll
        for (int kk = 0; kk < KTILE1; kk += 16) {
            const int colb = colb0 + kk * 2;
            uint32_t a[4][4], bf[2][4];
#pragma unroll
            for (int j = 0; j < 2; ++j) {
                uint32_t off = (uint32_t)((brow + j * 16) * 128 + colb);
                ldsm4(bf[j], tb_ + SWZ128(off));
            }
#pragma unroll
            for (int mi = 0; mi < 4; ++mi) {
                uint32_t off = (uint32_t)((arow + mi * 16) * 128 + colb);
                ldsm4(a[mi], ta_hi + SWZ128(off));
            }
#pragma unroll
            for (int mi = 0; mi < 4; ++mi)
#pragma unroll
                for (int nj = 0; nj < 4; ++nj)
                    mma_f16(acc[mi][nj], a[mi], bf[nj >> 1][nj & 1], bf[nj >> 1][2 + (nj & 1)]);
#pragma unroll
            for (int mi = 0; mi < 4; ++mi) {
                uint32_t off = (uint32_t)((arow + mi * 16) * 128 + colb);
                ldsm4(a[mi], ta_lo + SWZ128(off));
            }
#pragma unroll
            for (int mi = 0; mi < 4; ++mi)
#pragma unroll
                for (int nj = 0; nj < 4; ++nj)
                    mma_f16(acc[mi][nj], a[mi], bf[nj >> 1][nj & 1], bf[nj >> 1][2 + (nj & 1)]);
        }
    }

    // epilogue: write + stash for mirror
    const int r = lane >> 2;
    const int c = (lane & 3) * 2;
    const int mb = m0 + warp_m * 64;
    const int nb = n0 + warp_n * 32;

    __syncthreads();
    unsigned short* tbuf = reinterpret_cast<unsigned short*>(smem);

#pragma unroll
    for (int mi = 0; mi < 4; ++mi)
#pragma unroll
        for (int nj = 0; nj < 4; ++nj) {
            int row = mb + mi * 16 + r;
            int col = nb + nj * 8 + c;
            float d0 = acc[mi][nj][0], d1 = acc[mi][nj][1];
            float d2 = acc[mi][nj][2], d3 = acc[mi][nj][3];
            long o0 = bz * sC + (long)row * ldc + col;
            long o1 = bz * sC + (long)(row + 8) * ldc + col;
            __half h0 = __float2half_rn(d0), h1 = __float2half_rn(d1);
            __half h2 = __float2half_rn(d2), h3 = __float2half_rn(d3);
            *reinterpret_cast<__half2*>(Ch + o0) = __half2(h0, h1);
            *reinterpret_cast<__half2*>(Ch + o1) = __half2(h2, h3);
            int rl = row - m0, cl = col - n0;
            tbuf[rl * 130 + cl] = __half_as_ushort(h0);
            tbuf[rl * 130 + cl + 1] = __half_as_ushort(h1);
            tbuf[(rl + 8) * 130 + cl] = __half_as_ushort(h2);
            tbuf[(rl + 8) * 130 + cl + 1] = __half_as_ushort(h3);
        }

    if (bi < bj) {
        __syncthreads();
        for (int j = tid; j < 8192; j += 256) {
            int rp = j >> 6;
            int cp2 = (j & 63) << 1;
            __half2 hv(__ushort_as_half(tbuf[cp2 * 130 + rp]),
                       __ushort_as_half(tbuf[(cp2 + 1) * 130 + rp]));
            long o = bz * sC + (long)(n0 + rp) * ldc + (m0 + cp2);
            *reinterpret_cast<__half2*>(Ch + o) = hv;
        }
    }
}

// ---------------- big-tile GEMM (GEMM2 + GEMM3) ------------------------------
// C = A . B^T, single fp16 operands. CTA 128(M)x256(N), warp tile 64x64,
// KTILE=32 (64B rows), 4-stage cp.async, occ 1.
// MODE 0: fp32 out.  MODE 1: fp16 out.

#define KT_B 32
#define A_TILE_B 8192                   // 128 * 64 B
#define B_TILE_B 16384                  // 256 * 64 B
#define STG_B (A_TILE_B + B_TILE_B)     // 24 KB
#define SMEMB_TOT (4 * STG_B)           // 96 KB

template <int MODE>
__global__ __launch_bounds__(256, 1) void gemm_big(
    const __half* __restrict__ A, const __half* __restrict__ Bm,
    float* __restrict__ C, __half* __restrict__ Ch,
    int K, int lda, int ldb, int ldc, long sA, long sB, long sC, float cscale)
{
    extern __shared__ __align__(1024) unsigned char smem[];
    const uint32_t sbase = smem_u32(smem);
    const int tid = threadIdx.x;
    const int wid = tid >> 5;
    const int lane = tid & 31;
    const int warp_m = wid >> 2;   // 0..1
    const int warp_n = wid & 3;    // 0..3
    const int bz = blockIdx.z;
    const int m0 = blockIdx.y * 128;
    const int n0 = blockIdx.x * 256;

    const __half* srcA = A + bz * sA + (long)m0 * lda;
    const __half* srcB = Bm + bz * sB + (long)n0 * ldb;

    const int lr = lane & 7;
    const int lg = (lane >> 3) & 1;
    const int lk = (lane >> 4) & 1;
    const int arow = warp_m * 64 + lr + lg * 8;
    const int brow = warp_n * 64 + lr + lg * 8;
    const int colb0 = lk * 16;

    float acc[4][8][4];
#pragma unroll
    for (int i = 0; i < 4; ++i)
#pragma unroll
        for (int j = 0; j < 8; ++j)
#pragma unroll
            for (int c = 0; c < 4; ++c) acc[i][j][c] = 0.0f;

    const int T = K / KT_B;

    auto load_tile = [&](int p, int k0) {
        uint32_t dst0 = sbase + (uint32_t)p * STG_B;
#pragma unroll
        for (int i = 0; i < 6; ++i) {
            int cid = tid + i * 256;      // 0..1535
            if (cid < 512) {
                int row = cid >> 2, ck = cid & 3;
                const __half* src = srcA + (long)row * lda + k0 + ck * 8;
                uint32_t off = (uint32_t)(row * 64 + ck * 16);
                cp_async16(dst0 + SWZ128(off), src);
            } else {
                int idx = cid - 512;
                int row = idx >> 2, ck = idx & 3;
                const __half* src = srcB + (long)row * ldb + k0 + ck * 8;
                uint32_t off = (uint32_t)(row * 64 + ck * 16);
                cp_async16(dst0 + A_TILE_B + SWZ128(off), src);
            }
        }
        asm volatile("cp.async.commit_group;");
    };

    load_tile(0, 0);
    load_tile(1, KT_B);
    load_tile(2, 2 * KT_B);

    for (int t = 0; t < T; ++t) {
        int rem = T - 1 - t;
        if (rem >= 2)      asm volatile("cp.async.wait_group 2;");
        else if (rem == 1) asm volatile("cp.async.wait_group 1;");
        else               asm volatile("cp.async.wait_group 0;");
        __syncthreads();
        if (t + 3 < T) load_tile((t + 3) & 3, (t + 3) * KT_B);

        const uint32_t st = sbase + (uint32_t)(t & 3) * STG_B;
        const uint32_t ta = st;
        const uint32_t tb = st + A_TILE_B;

#pragma unroll
        for (int kk = 0; kk < KT_B; kk += 16) {
            const int colb = colb0 + kk * 2;
            uint32_t a[4][4], bf[4][4];
#pragma unroll
            for (int j = 0; j < 4; ++j) {
                uint32_t off = (uint32_t)((brow + j * 16) * 64 + colb);
                ldsm4(bf[j], tb + SWZ128(off));
            }
#pragma unroll
            for (int mi = 0; mi < 4; ++mi) {
                uint32_t off = (uint32_t)((arow + mi * 16) * 64 + colb);
                ldsm4(a[mi], ta + SWZ128(off));
            }
#pragma unroll
            for (int mi = 0; mi < 4; ++mi)
#pragma unroll
                for (int nj = 0; nj < 8; ++nj)
                    mma_f16(acc[mi][nj], a[mi], bf[nj >> 1][nj & 1], bf[nj >> 1][2 + (nj & 1)]);
        }
    }

    // epilogue
    const int r = lane >> 2;
    const int c = (lane & 3) * 2;
    const int mb = m0 + warp_m * 64;
    const int nb = n0 + warp_n * 64;

#pragma unroll
    for (int mi = 0; mi < 4; ++mi)
#pragma unroll
        for (int nj = 0; nj < 8; ++nj) {
            int row = mb + mi * 16 + r;
            int col = nb + nj * 8 + c;
            float d0 = acc[mi][nj][0] * cscale, d1 = acc[mi][nj][1] * cscale;
            float d2 = acc[mi][nj][2] * cscale, d3 = acc[mi][nj][3] * cscale;
            if (MODE == 0) {
                float* cp = C + bz * sC + (long)row * ldc + col;
                *reinterpret_cast<float2*>(cp) = make_float2(d0, d1);
                float* cp2 = C + bz * sC + (long)(row + 8) * ldc + col;
                *reinterpret_cast<float2*>(cp2) = make_float2(d2, d3);
            } else {
                long o0 = bz * sC + (long)row * ldc + col;
                long o1 = bz * sC + (long)(row + 8) * ldc + col;
                *reinterpret_cast<__half2*>(Ch + o0) =
                    __half2(__float2half_rn(d0), __float2half_rn(d1));
                *reinterpret_cast<__half2*>(Ch + o1) =
                    __half2(__float2half_rn(d2), __float2half_rn(d3));
            }
        }
}

// ---------------- launch -----------------------------------------------------
extern "C" void kernel_launch(void* const* d_in, const int* in_sizes, int n_in,
                              void* d_out, int out_size) {
    const float* x = (const float*)d_in[0];
    const float* W = (const float*)d_in[1];
    float* out = (float*)d_out;

    const int S = S_DIM, H = H_DIM, B = B_DIM;
    const long HS = (long)H * S, HH = (long)H * H, SH = (long)S * H;

    __half *xhi, *xThi, *xTlo, *WThi, *Ghi, *MThi;
    cudaGetSymbolAddress((void**)&xhi, g_xhi);
    cudaGetSymbolAddress((void**)&xThi, g_xThi);
    cudaGetSymbolAddress((void**)&xTlo, g_xTlo);
    cudaGetSymbolAddress((void**)&WThi, g_WThi);
    cudaGetSymbolAddress((void**)&Ghi, g_Ghi);
    cudaGetSymbolAddress((void**)&MThi, g_MThi);

    cudaFuncSetAttribute(gemm_sym, cudaFuncAttributeMaxDynamicSharedMemorySize, SMEM1_TOT);
    cudaFuncSetAttribute(gemm_big<0>, cudaFuncAttributeMaxDynamicSharedMemorySize, SMEMB_TOT);
    cudaFuncSetAttribute(gemm_big<1>, cudaFuncAttributeMaxDynamicSharedMemorySize, SMEMB_TOT);

    // conversions
    x_conv_kernel<<<dim3(H / 32, S / 32, B), dim3(32, 8)>>>(x, xhi, xThi, xTlo, S, H);
    w_conv_kernel<<<dim3(H / 32, H / 32, 1), dim3(32, 8)>>>(W, WThi, H, H, 4096.0f);

    // GEMM1 (symmetric, A split): G = (xThi+xTlo) . xThi^T,  K=S, upper-tri
    gemm_sym<<<dim3(36, 1, B), 256, SMEM1_TOT>>>(
        xThi, xTlo, xThi, Ghi, S, S, H, HS, HH);

    // GEMM2: MT[h][k] = G[h][.] . WT[k][.]^T ; carries W's x4096 scale
    gemm_big<1><<<dim3(H / 256, H / 128, B), 256, SMEMB_TOT>>>(
        Ghi, WThi, nullptr, MThi,
        H, H, H, H, HH, 0L, HH, 1.0f);

    // GEMM3: out = xhi . MT^T ; undo x4096
    gemm_big<0><<<dim3(H / 256, S / 128, B), 256, SMEMB_TOT>>>(
        xhi, MThi, out, nullptr,
        H, H, H, H, SH, HH, SH, 1.0f / 4096.0f);
}

// round 13
// speedup vs baseline: 1.3866x; 1.3866x over previous
#include <cuda_runtime.h>
#include <cuda_fp16.h>
#include <cstdint>

#define S_DIM 4096
#define H_DIM 1024
#define B_DIM 4

// ---------------- scratch (__device__ globals; no allocs allowed) -----------
__device__ __half g_xhi [B_DIM * S_DIM * H_DIM];
__device__ __half g_xThi[B_DIM * H_DIM * S_DIM];
__device__ __half g_WThi[H_DIM * H_DIM];
__device__ __half g_Ghi [B_DIM * H_DIM * H_DIM];
__device__ __half g_MThi[B_DIM * H_DIM * H_DIM];

// ---------------- helpers ----------------------------------------------------
__device__ __forceinline__ uint32_t smem_u32(const void* p) {
    uint32_t a;
    asm("{ .reg .u64 t; cvta.to.shared.u64 t, %1; cvt.u32.u64 %0, t; }"
        : "=r"(a) : "l"(p));
    return a;
}

#define SWZ128(off) ((off) ^ (((off) >> 3) & 0x70))

__device__ __forceinline__ void cp_async16(uint32_t dst, const void* src) {
    asm volatile("cp.async.cg.shared.global [%0], [%1], 16;" :: "r"(dst), "l"(src));
}

__device__ __forceinline__ void ldsm4(uint32_t* r, uint32_t addr) {
    asm volatile("ldmatrix.sync.aligned.m8n8.x4.shared.b16 {%0,%1,%2,%3}, [%4];"
                 : "=r"(r[0]), "=r"(r[1]), "=r"(r[2]), "=r"(r[3]) : "r"(addr));
}

__device__ __forceinline__ void mma_f16(float* d, const uint32_t* a,
                                        uint32_t b0, uint32_t b1) {
    asm volatile(
        "mma.sync.aligned.m16n8k16.row.col.f32.f16.f16.f32 "
        "{%0,%1,%2,%3}, {%4,%5,%6,%7}, {%8,%9}, {%0,%1,%2,%3};"
        : "+f"(d[0]), "+f"(d[1]), "+f"(d[2]), "+f"(d[3])
        : "r"(a[0]), "r"(a[1]), "r"(a[2]), "r"(a[3]), "r"(b0), "r"(b1));
}

// ---------------- conversion kernels ----------------------------------------
// x: natural hi [R][C] + transposed hi [C][R].  blockDim = (32, 8)
__global__ void x_conv_kernel(const float* __restrict__ in,
                              __half* __restrict__ hiN,
                              __half* __restrict__ hiT,
                              int R, int C) {
    __shared__ float tile[32][33];
    long boff = (long)blockIdx.z * R * C;
    const float* src = in + boff;
    int bx = blockIdx.x * 32;
    int by = blockIdx.y * 32;
    int tx = threadIdx.x, ty = threadIdx.y;
#pragma unroll
    for (int j = 0; j < 4; ++j) {
        int row = by + ty + j * 8;
        float v = src[(long)row * C + bx + tx];
        tile[ty + j * 8][tx] = v;
        hiN[boff + (long)row * C + bx + tx] = __float2half_rn(v);
    }
    __syncthreads();
#pragma unroll
    for (int j = 0; j < 4; ++j) {
        int oc = bx + ty + j * 8;
        int orow = by + tx;
        hiT[boff + (long)oc * R + orow] = __float2half_rn(tile[tx][ty + j * 8]);
    }
}

// W: transposed hi only, pre-scaled (x4096 keeps fp16 normal).
__global__ void w_conv_kernel(const float* __restrict__ in,
                              __half* __restrict__ hiT, int R, int C, float sc) {
    __shared__ float tile[32][33];
    int bx = blockIdx.x * 32;
    int by = blockIdx.y * 32;
    int tx = threadIdx.x, ty = threadIdx.y;
#pragma unroll
    for (int j = 0; j < 4; ++j)
        tile[ty + j * 8][tx] = in[(long)(by + ty + j * 8) * C + bx + tx];
    __syncthreads();
#pragma unroll
    for (int j = 0; j < 4; ++j) {
        int oc = bx + ty + j * 8;
        int orow = by + tx;
        hiT[(long)oc * R + orow] = __float2half_rn(tile[tx][ty + j * 8] * sc);
    }
}

// ---------------- HMMA GEMM (R11 engine) --------------------------------------
// C = P0 . PB^T, single fp16 operands, 3-stage cp.async, 2 CTA/SM, 8 warps 2x4.
// CTA tile 128x128, KTILE=64 fp16 (128B rows, SW128).
// MODE 0: fp32 C.  MODE 1: fp16 C.  MODE 2: fp16 C, symmetric mirror (A==B).

#define KTILE 64
#define TILE_B 16384                 // 128 rows * 128 B
#define STAGE_B (2 * TILE_B)         // A, B
#define SMEM_TOT (3 * STAGE_B)       // 96 KB

template <int MODE>
__global__ __launch_bounds__(256, 2) void gemm_hmma(
    const __half* __restrict__ P0, const __half* __restrict__ PB,
    float* __restrict__ C, __half* __restrict__ Ch,
    int K, int lda, int ldb, int ldc,
    long s0, long sB, long sC, float cscale)
{
    extern __shared__ __align__(1024) unsigned char smem[];
    const uint32_t sbase = smem_u32(smem);
    const int tid = threadIdx.x;
    const int wid = tid >> 5;
    const int lane = tid & 31;
    const int warp_m = wid >> 2;
    const int warp_n = wid & 3;
    const int bz = blockIdx.z;

    int m0, n0, bi = 0, bj = 0;
    if (MODE == 2) {
        int r = blockIdx.x;
        while (r >= 8 - bi) { r -= 8 - bi; ++bi; }
        bj = bi + r;
        m0 = bi * 128; n0 = bj * 128;
    } else {
        m0 = blockIdx.y * 128; n0 = blockIdx.x * 128;
    }

    const __half* srcA = P0 + bz * s0 + (long)m0 * lda;
    const __half* srcB = PB + bz * sB + (long)n0 * ldb;

    const int lr = lane & 7;
    const int lg = (lane >> 3) & 1;
    const int lk = (lane >> 4) & 1;
    const int arow = warp_m * 64 + lr + lg * 8;
    const int brow = warp_n * 32 + lr + lg * 8;
    const int colb0 = lk * 16;

    float acc[4][4][4];
#pragma unroll
    for (int i = 0; i < 4; ++i)
#pragma unroll
        for (int j = 0; j < 4; ++j)
#pragma unroll
            for (int c = 0; c < 4; ++c) acc[i][j][c] = 0.0f;

    const int T = K / KTILE;

    auto load_tile = [&](int p, int k0) {
        uint32_t dst0 = sbase + (uint32_t)p * STAGE_B;
#pragma unroll
        for (int i = 0; i < 8; ++i) {
            int cid = tid + i * 256;      // 0..2047
            int idx = cid & 1023;
            int row = idx >> 3;
            int ck = idx & 7;
            uint32_t off = (uint32_t)(row * 128 + ck * 16);
            if (cid < 1024) {
                cp_async16(dst0 + SWZ128(off), srcA + (long)row * lda + k0 + ck * 8);
            } else {
                cp_async16(dst0 + TILE_B + SWZ128(off), srcB + (long)row * ldb + k0 + ck * 8);
            }
        }
        asm volatile("cp.async.commit_group;");
    };

    load_tile(0, 0);
    if (T > 1) load_tile(1, KTILE);

    for (int t = 0; t < T; ++t) {
        if (t + 1 < T) asm volatile("cp.async.wait_group 1;");
        else           asm volatile("cp.async.wait_group 0;");
        __syncthreads();
        if (t + 2 < T) load_tile((t + 2) % 3, (t + 2) * KTILE);

        const uint32_t st = sbase + (uint32_t)(t % 3) * STAGE_B;
        const uint32_t ta = st;
        const uint32_t tb = st + TILE_B;

#pragma unroll
        for (int kk = 0; kk < KTILE; kk += 16) {
            const int colb = colb0 + kk * 2;
            uint32_t a[4][4], bf[2][4];
#pragma unroll
            for (int j = 0; j < 2; ++j) {
                uint32_t off = (uint32_t)((brow + j * 16) * 128 + colb);
                ldsm4(bf[j], tb + SWZ128(off));
            }
#pragma unroll
            for (int mi = 0; mi < 4; ++mi) {
                uint32_t off = (uint32_t)((arow + mi * 16) * 128 + colb);
                ldsm4(a[mi], ta + SWZ128(off));
            }
#pragma unroll
            for (int mi = 0; mi < 4; ++mi)
#pragma unroll
                for (int nj = 0; nj < 4; ++nj)
                    mma_f16(acc[mi][nj], a[mi], bf[nj >> 1][nj & 1], bf[nj >> 1][2 + (nj & 1)]);
        }
    }

    // ---------------- epilogue ----------------
    const int r = lane >> 2;
    const int c = (lane & 3) * 2;
    const int mb = m0 + warp_m * 64;
    const int nb = n0 + warp_n * 32;

    if (MODE == 2) __syncthreads();   // pipeline smem dead; mirror buffer reuse
    unsigned short* tbuf = reinterpret_cast<unsigned short*>(smem);

#pragma unroll
    for (int mi = 0; mi < 4; ++mi)
#pragma unroll
        for (int nj = 0; nj < 4; ++nj) {
            int row = mb + mi * 16 + r;
            int col = nb + nj * 8 + c;
            float d0 = acc[mi][nj][0] * cscale, d1 = acc[mi][nj][1] * cscale;
            float d2 = acc[mi][nj][2] * cscale, d3 = acc[mi][nj][3] * cscale;
            if (MODE == 0) {
                float* cp = C + bz * sC + (long)row * ldc + col;
                *reinterpret_cast<float2*>(cp) = make_float2(d0, d1);
                float* cp2 = C + bz * sC + (long)(row + 8) * ldc + col;
                *reinterpret_cast<float2*>(cp2) = make_float2(d2, d3);
            } else {
                long o0 = bz * sC + (long)row * ldc + col;
                long o1 = bz * sC + (long)(row + 8) * ldc + col;
                __half h0 = __float2half_rn(d0), h1 = __float2half_rn(d1);
                __half h2 = __float2half_rn(d2), h3 = __float2half_rn(d3);
                *reinterpret_cast<__half2*>(Ch + o0) = __half2(h0, h1);
                *reinterpret_cast<__half2*>(Ch + o1) = __half2(h2, h3);
                if (MODE == 2) {
                    int rl = row - m0, cl = col - n0;
                    tbuf[rl * 130 + cl] = __half_as_ushort(h0);
                    tbuf[rl * 130 + cl + 1] = __half_as_ushort(h1);
                    tbuf[(rl + 8) * 130 + cl] = __half_as_ushort(h2);
                    tbuf[(rl + 8) * 130 + cl + 1] = __half_as_ushort(h3);
                }
            }
        }

    if (MODE == 2 && bi < bj) {
        __syncthreads();
        for (int j = tid; j < 8192; j += 256) {
            int rp = j >> 6;
            int cp2 = (j & 63) << 1;
            __half2 hv(__ushort_as_half(tbuf[cp2 * 130 + rp]),
                       __ushort_as_half(tbuf[(cp2 + 1) * 130 + rp]));
            long o = bz * sC + (long)(n0 + rp) * ldc + (m0 + cp2);
            *reinterpret_cast<__half2*>(Ch + o) = hv;
        }
    }
}

// ---------------- launch -----------------------------------------------------
extern "C" void kernel_launch(void* const* d_in, const int* in_sizes, int n_in,
                              void* d_out, int out_size) {
    const float* x = (const float*)d_in[0];
    const float* W = (const float*)d_in[1];
    float* out = (float*)d_out;

    const int S = S_DIM, H = H_DIM, B = B_DIM;
    const long HS = (long)H * S, HH = (long)H * H, SH = (long)S * H;

    __half *xhi, *xThi, *WThi, *Ghi, *MThi;
    cudaGetSymbolAddress((void**)&xhi, g_xhi);
    cudaGetSymbolAddress((void**)&xThi, g_xThi);
    cudaGetSymbolAddress((void**)&WThi, g_WThi);
    cudaGetSymbolAddress((void**)&Ghi, g_Ghi);
    cudaGetSymbolAddress((void**)&MThi, g_MThi);

    cudaFuncSetAttribute(gemm_hmma<0>, cudaFuncAttributeMaxDynamicSharedMemorySize, SMEM_TOT);
    cudaFuncSetAttribute(gemm_hmma<1>, cudaFuncAttributeMaxDynamicSharedMemorySize, SMEM_TOT);
    cudaFuncSetAttribute(gemm_hmma<2>, cudaFuncAttributeMaxDynamicSharedMemorySize, SMEM_TOT);

    // conversions
    x_conv_kernel<<<dim3(H / 32, S / 32, B), dim3(32, 8)>>>(x, xhi, xThi, S, H);
    w_conv_kernel<<<dim3(H / 32, H / 32, 1), dim3(32, 8)>>>(W, WThi, H, H, 4096.0f);

    // GEMM1 (symmetric, single-rounded): G = xThi . xThi^T, K=S, upper-tri
    gemm_hmma<2><<<dim3(36, 1, B), 256, SMEM_TOT>>>(
        xThi, xThi, nullptr, Ghi,
        S, S, S, H, HS, HS, HH, 1.0f);

    // GEMM2: MT[h][k] = G[h][.] . WT[k][.]^T ; carries W's x4096 scale
    gemm_hmma<1><<<dim3(8, 8, B), 256, SMEM_TOT>>>(
        Ghi, WThi, nullptr, MThi,
        H, H, H, H, HH, 0L, HH, 1.0f);

    // GEMM3: out = xhi . MT^T ; undo x4096
    gemm_hmma<0><<<dim3(8, 32, B), 256, SMEM_TOT>>>(
        xhi, MThi, out, nullptr,
        H, H, H, H, SH, HH, SH, 1.0f / 4096.0f);
}